// round 10
// baseline (speedup 1.0000x reference)
#include <cuda_runtime.h>
#include <cuda_bf16.h>
#include <cstdint>
#include <math.h>

#define B     64
#define LA    8
#define H     512
#define V     16384
#define SS    316
#define CTXN  256
#define NROWS (B*LA)
#define SCALE 0.04419417382415922f   // 512^-0.5
#define NZROWS 60
#define MAXNZ  16

// ---------------- device scratch ----------------
__device__ __align__(16) float g_gen_exp[(size_t)NROWS * V];
__device__ float g_copy_exp[NROWS * SS];
__device__ float g_rowsum[NROWS];
__device__ __align__(16) __nv_bfloat16 g_Abf[NROWS * H];       // dec bf16
__device__ __align__(16) __nv_bfloat16 g_Wt[(size_t)V * H];    // W^T bf16, K-major
__device__ int2 g_nz[NZROWS * B * MAXNZ];                      // (v, fp32 bits)
__device__ int  g_nzc[NZROWS * B];

// ---------------- helpers ----------------
__device__ __forceinline__ uint32_t smem_u32(const void* p) {
    uint32_t a;
    asm("{ .reg .u64 t; cvta.to.shared.u64 t, %1; cvt.u32.u64 %0, t; }" : "=r"(a) : "l"(p));
    return a;
}
__device__ __forceinline__ void ldmx4(uint32_t* r, uint32_t addr) {
    asm volatile("ldmatrix.sync.aligned.m8n8.x4.shared.b16 {%0,%1,%2,%3}, [%4];"
        : "=r"(r[0]), "=r"(r[1]), "=r"(r[2]), "=r"(r[3]) : "r"(addr));
}
__device__ __forceinline__ void mma16816(float* d, const uint32_t* a, uint32_t b0, uint32_t b1) {
    asm volatile("mma.sync.aligned.m16n8k16.row.col.f32.bf16.bf16.f32 "
        "{%0,%1,%2,%3}, {%4,%5,%6,%7}, {%8,%9}, {%0,%1,%2,%3};"
        : "+f"(d[0]), "+f"(d[1]), "+f"(d[2]), "+f"(d[3])
        : "r"(a[0]), "r"(a[1]), "r"(a[2]), "r"(a[3]), "r"(b0), "r"(b1));
}
__device__ __forceinline__ void cp_async16(uint32_t dst, const void* src) {
    asm volatile("cp.async.cg.shared.global [%0], [%1], 16;" :: "r"(dst), "l"(src));
}
#define CP_COMMIT() asm volatile("cp.async.commit_group;")
#define CP_WAIT(n)  asm volatile("cp.async.wait_group %0;" :: "n"(n))

__device__ __forceinline__ float4 ldcs4(const float* p) {
    float4 v;
    asm volatile("ld.global.cs.v4.f32 {%0,%1,%2,%3}, [%4];"
        : "=f"(v.x), "=f"(v.y), "=f"(v.z), "=f"(v.w) : "l"(p));
    return v;
}

// ---------------- Kc_A: dec fp32 -> bf16 (+ zero rowsums) ----------------
__global__ void kc_A(const float* __restrict__ dec) {
    int i = blockIdx.x * 256 + threadIdx.x;
    g_Abf[i] = __float2bfloat16(dec[i]);
    if (i < NROWS) g_rowsum[i] = 0.f;
}

// ---------------- Kc_W: W[K,V] -> Wt[V,K] bf16 ----------------
__global__ __launch_bounds__(256) void kc_W(const float* __restrict__ W) {
    __shared__ float t[64][33];
    int n0 = blockIdx.x * 32, k0 = blockIdx.y * 64;
    int tx = threadIdx.x & 31, ty = threadIdx.x >> 5;
    for (int i = ty; i < 64; i += 8)
        t[i][tx] = W[(size_t)(k0 + i) * V + n0 + tx];
    __syncthreads();
    for (int i = ty; i < 32; i += 8) {
        __nv_bfloat162 h2;
        h2.x = __float2bfloat16(t[2 * tx][i]);
        h2.y = __float2bfloat16(t[2 * tx + 1][i]);
        *(__nv_bfloat162*)&g_Wt[(size_t)(n0 + i) * H + k0 + 2 * tx] = h2;
    }
}

// ---------------- K1: copy logits -> exp + row sums (thread per s) --------
#define K1_T 160
__global__ __launch_bounds__(K1_T) void k1_copy(const float* __restrict__ dec,
                                                const float* __restrict__ srch,
                                                const int* __restrict__ mask) {
    __shared__ float4 dsm[LA][H / 4];
    __shared__ float lsum[LA];
    int b = blockIdx.x;
    int tid = threadIdx.x;
    const float4* dg = (const float4*)(dec + (size_t)b * LA * H);
    for (int i = tid; i < LA * H / 4; i += K1_T)
        ((float4*)dsm)[i] = dg[i];
    if (tid < LA) lsum[tid] = 0.f;
    __syncthreads();

    int s = blockIdx.y * K1_T + tid;
    bool valid = (s < SS);
    int m = valid ? mask[b * SS + s] : 0;

    float acc[LA];
    #pragma unroll
    for (int l = 0; l < LA; l++) acc[l] = 0.f;

    if (m != 0) {
        const float4* vp = (const float4*)(srch + ((size_t)b * SS + s) * H);
        #pragma unroll 8
        for (int h4 = 0; h4 < H / 4; h4 += 2) {
            float4 v0 = vp[h4], v1 = vp[h4 + 1];
            #pragma unroll
            for (int l = 0; l < LA; l++) {
                float4 d0 = dsm[l][h4];
                acc[l] += d0.x * v0.x + d0.y * v0.y + d0.z * v0.z + d0.w * v0.w;
                float4 d1 = dsm[l][h4 + 1];
                acc[l] += d1.x * v1.x + d1.y * v1.y + d1.z * v1.z + d1.w * v1.w;
            }
        }
    }

    #pragma unroll
    for (int l = 0; l < LA; l++) {
        float e = (m != 0) ? __expf(acc[l] * SCALE) : 0.f;
        if (valid) g_copy_exp[(b * LA + l) * SS + s] = e;
        float r = e;
        #pragma unroll
        for (int off = 16; off; off >>= 1) r += __shfl_xor_sync(0xffffffffu, r, off);
        if ((tid & 31) == 0) atomicAdd(&lsum[l], r);
    }
    __syncthreads();
    if (tid < LA) atomicAdd(&g_rowsum[b * LA + tid], lsum[tid]);
}

// ---------------- K2: warp-MMA bf16 GEMM, warp tile 64x64 -----------------
#define PITCH 40
#define STG 3
#define TILE_HALFS (128 * PITCH)
#define K2_SMEM (STG * 2 * TILE_HALFS * 2)  // 61440 B
__global__ __launch_bounds__(128) void k2m(const float* __restrict__ bias) {
    extern __shared__ __align__(16) __nv_bfloat16 sm[];
    __nv_bfloat16* As = sm;
    __nv_bfloat16* Bs = sm + STG * TILE_HALFS;

    int tid = threadIdx.x, wid = tid >> 5, lane = tid & 31;
    int bx = blockIdx.x, by = blockIdx.y;
    int wm = wid >> 1, wn = wid & 1;

    const __nv_bfloat16* Ag = g_Abf + (size_t)(by * 128) * H;
    const __nv_bfloat16* Bg = g_Wt + (size_t)(bx * 128) * H;

    float acc[4][8][4];
    #pragma unroll
    for (int i = 0; i < 4; i++)
        #pragma unroll
        for (int j = 0; j < 8; j++)
            #pragma unroll
            for (int k = 0; k < 4; k++) acc[i][j][k] = 0.f;

    int ldr = tid >> 2, ldc8 = (tid & 3) * 8;

    #define ISSUE(KT, BUF) do {                                                       \
        _Pragma("unroll")                                                              \
        for (int q = 0; q < 4; q++) {                                                  \
            int _r = ldr + 32 * q;                                                     \
            cp_async16(smem_u32(&As[(BUF) * TILE_HALFS + _r * PITCH + ldc8]),          \
                       Ag + (size_t)_r * H + (KT) * 32 + ldc8);                        \
            cp_async16(smem_u32(&Bs[(BUF) * TILE_HALFS + _r * PITCH + ldc8]),          \
                       Bg + (size_t)_r * H + (KT) * 32 + ldc8);                        \
        }                                                                              \
        CP_COMMIT();                                                                   \
    } while (0)

    ISSUE(0, 0); ISSUE(1, 1);

    int g = lane >> 3, r = lane & 7;
    uint32_t a0[4], b0[4];
    #pragma unroll
    for (int mt = 0; mt < 4; mt++)
        a0[mt] = smem_u32(&As[(wm * 64 + mt * 16 + (g & 1) * 8 + r) * PITCH + (g >> 1) * 8]);
    #pragma unroll
    for (int nq = 0; nq < 4; nq++)
        b0[nq] = smem_u32(&Bs[(wn * 64 + nq * 16 + (g >> 1) * 8 + r) * PITCH + (g & 1) * 8]);

    for (int kt = 0; kt < 16; kt++) {
        if (kt < 15) CP_WAIT(1); else CP_WAIT(0);
        __syncthreads();
        if (kt + 2 < 16) {
            int nb = (kt + 2) % STG;
            ISSUE(kt + 2, nb);
        }

        uint32_t soff = (uint32_t)(kt % STG) * (TILE_HALFS * 2);
        #pragma unroll
        for (int kk = 0; kk < 2; kk++) {
            uint32_t ko = soff + kk * 32;
            uint32_t afr[4][4];
            #pragma unroll
            for (int mt = 0; mt < 4; mt++) ldmx4(afr[mt], a0[mt] + ko);
            uint32_t bfr[4][4];
            #pragma unroll
            for (int nq = 0; nq < 4; nq++) ldmx4(bfr[nq], b0[nq] + ko);
            #pragma unroll
            for (int mt = 0; mt < 4; mt++)
                #pragma unroll
                for (int nt = 0; nt < 8; nt++)
                    mma16816(acc[mt][nt], afr[mt],
                             bfr[nt >> 1][(nt & 1) * 2], bfr[nt >> 1][(nt & 1) * 2 + 1]);
        }
    }

    int r4 = lane >> 2, c2 = (lane & 3) * 2;
    #pragma unroll
    for (int mt = 0; mt < 4; mt++) {
        float rs0 = 0.f, rs1 = 0.f;
        #pragma unroll
        for (int nt = 0; nt < 8; nt++) {
            int col = bx * 128 + wn * 64 + nt * 8 + c2;
            float b0f = bias[col], b1f = bias[col + 1];
            int row0 = by * 128 + wm * 64 + mt * 16 + r4;
            float e0 = __expf((acc[mt][nt][0] + b0f) * SCALE);
            float e1 = __expf((acc[mt][nt][1] + b1f) * SCALE);
            *(float2*)&g_gen_exp[(size_t)row0 * V + col] = make_float2(e0, e1);
            rs0 += e0 + e1;
            float e2 = __expf((acc[mt][nt][2] + b0f) * SCALE);
            float e3 = __expf((acc[mt][nt][3] + b1f) * SCALE);
            *(float2*)&g_gen_exp[(size_t)(row0 + 8) * V + col] = make_float2(e2, e3);
            rs1 += e2 + e3;
        }
        #pragma unroll
        for (int off = 1; off < 4; off <<= 1) {
            rs0 += __shfl_xor_sync(0xffffffffu, rs0, off);
            rs1 += __shfl_xor_sync(0xffffffffu, rs1, off);
        }
        if ((lane & 3) == 0) {
            int row0 = by * 128 + wm * 64 + mt * 16 + r4;
            atomicAdd(&g_rowsum[row0], rs0);
            atomicAdd(&g_rowsum[row0 + 8], rs1);
        }
    }
}

// ---------------- K_find: scan one-hot matrices -> compact nonzero lists --
__global__ __launch_bounds__(256) void k_find(const float* __restrict__ pv,
                                              const float* __restrict__ lmat,
                                              const float* __restrict__ tpm,
                                              const float* __restrict__ rel) {
    __shared__ int scnt;
    int rid = blockIdx.x;           // rid = row60 * B + b
    int b = rid & (B - 1), row = rid >> 6;
    int tid = threadIdx.x;
    if (tid == 0) scnt = 0;
    __syncthreads();

    const float* base;
    int p, np;
    if (row < 10)      { base = pv;   p = row;      np = 10; }
    else if (row < 20) { base = lmat; p = row - 10; np = 10; }
    else if (row < 30) { base = tpm;  p = row - 20; np = 10; }
    else               { base = rel;  p = row - 30; np = 30; }
    const float* mrow = base + ((size_t)b * np + p) * V;

    #pragma unroll
    for (int q = 0; q < 16; q++) {
        int v4 = q * 256 + tid;
        float4 m = ldcs4(&mrow[(size_t)v4 * 4]);
        float mv[4] = {m.x, m.y, m.z, m.w};
        #pragma unroll
        for (int c = 0; c < 4; c++) {
            if (mv[c] != 0.f) {
                int pos = atomicAdd(&scnt, 1);
                if (pos < MAXNZ)
                    g_nz[rid * MAXNZ + pos] = make_int2(v4 * 4 + c, __float_as_int(mv[c]));
            }
        }
    }
    __syncthreads();
    if (tid == 0) g_nzc[rid] = (scnt < MAXNZ) ? scnt : MAXNZ;
}

// ---------------- K4f: fused scatter (smem) + ctx + normalize -------------
// One block per output row (b,l). All scatter targets are row-local, so the
// ~316 sparse adds stage in a 64KB smem accumulator, then one fused pass:
// out = (gen_exp + sadd) * invZ.
#define K4F_SMEM (V * 4)
__global__ __launch_bounds__(256) void k4f(const int* __restrict__ ctx,
                                           const int* __restrict__ g2l,
                                           float* __restrict__ out) {
    extern __shared__ float sadd[];   // V floats
    int row = blockIdx.x;             // = b*LA + l
    int b = row >> 3;
    int tid = threadIdx.x;

    float4* s4 = (float4*)sadd;
    #pragma unroll 4
    for (int i = tid; i < V / 4; i += 256)
        s4[i] = make_float4(0.f, 0.f, 0.f, 0.f);
    __syncthreads();

    // one-hot contributions (60 rows, compact lists from k_find)
    if (tid < NZROWS) {
        int r60 = tid;
        int rid = r60 * B + b;
        int src = (r60 < 30) ? r60 : r60 + CTXN;
        float pc = g_copy_exp[row * SS + src];
        int cnt = g_nzc[rid];
        for (int j = 0; j < cnt; j++) {
            int2 e = g_nz[rid * MAXNZ + j];
            atomicAdd(&sadd[e.x], pc * __int_as_float(e.y));
        }
    }
    // ctx contributions (256 slots)
    {
        int tgt = g2l[ctx[b * CTXN + tid]];
        atomicAdd(&sadd[tgt], g_copy_exp[row * SS + 30 + tid]);
    }
    __syncthreads();

    float z = 1.f / g_rowsum[row];
    const float* ge = &g_gen_exp[(size_t)row * V];
    float4* dst = (float4*)&out[(size_t)row * V];
    #pragma unroll 4
    for (int i = tid; i < V / 4; i += 256) {
        float4 v = ldcs4(ge + i * 4);
        float4 a = s4[i];
        v.x = (v.x + a.x) * z;
        v.y = (v.y + a.y) * z;
        v.z = (v.z + a.z) * z;
        v.w = (v.w + a.w) * z;
        dst[i] = v;
    }
}

// ---------------- launch (single stream) ----------------------------------
extern "C" void kernel_launch(void* const* d_in, const int* in_sizes, int n_in,
                              void* d_out, int out_size) {
    const float* dec  = (const float*)d_in[0];
    const float* srch = (const float*)d_in[1];
    const int*   mask = (const int*)  d_in[2];
    const float* pv   = (const float*)d_in[3];
    const float* lmat = (const float*)d_in[4];
    const float* tpm  = (const float*)d_in[5];
    const float* rel  = (const float*)d_in[6];
    const float* W    = (const float*)d_in[7];
    const float* bias = (const float*)d_in[8];
    const int*   ctx  = (const int*)  d_in[9];
    const int*   g2l  = (const int*)  d_in[10];
    float* out = (float*)d_out;

    cudaFuncSetAttribute(k2m, cudaFuncAttributeMaxDynamicSharedMemorySize, K2_SMEM);
    cudaFuncSetAttribute(k4f, cudaFuncAttributeMaxDynamicSharedMemorySize, K4F_SMEM);

    kc_A<<<NROWS * H / 256, 256>>>(dec);
    kc_W<<<dim3(V / 32, H / 64), 256>>>(W);
    k1_copy<<<dim3(B, 2), K1_T>>>(dec, srch, mask);
    k_find<<<NZROWS * B, 256>>>(pv, lmat, tpm, rel);
    k2m<<<dim3(V / 128, NROWS / 128), 128, K2_SMEM>>>(bias);
    k4f<<<NROWS, 256, K4F_SMEM>>>(ctx, g2l, out);
}